// round 2
// baseline (speedup 1.0000x reference)
#include <cuda_runtime.h>
#include <cstddef>

#define BSZ 32
#define SEQ 512
#define IND 512
#define HID 1024
#define G4  4096

// scratch: xU = x @ [Uf|Ui|Uo|Ug] + b   (layout [BSZ*SEQ][4096], 256 MiB)
__device__ float g_xU[(size_t)BSZ * SEQ * G4];
// transposed hidden-state history: g_hT[t][k][b]  (64 MiB)
__device__ float g_hT[(size_t)SEQ * HID * BSZ];
// grid-barrier flags (one word per block, reset each launch)
__device__ volatile unsigned g_flags[128];

// ------------------------------------------------------------------
// Phase A: xU[m][n] = sum_k X[m][k] * Ucat[k][n] + bcat[n]
// 128x128 block tile, BK=8, 256 threads, 8x8 register tile
// ------------------------------------------------------------------
__global__ __launch_bounds__(256) void gemm_xU_kernel(
    const float* __restrict__ X,
    const float* __restrict__ Uf, const float* __restrict__ Ui,
    const float* __restrict__ Uo, const float* __restrict__ Ug,
    const float* __restrict__ bf, const float* __restrict__ bi,
    const float* __restrict__ bo, const float* __restrict__ bg)
{
    __shared__ float As[8][128];
    __shared__ float Bs[8][128];

    const int tid = threadIdx.x;
    const int n0  = blockIdx.x * 128;     // [0, 4096)
    const int m0  = blockIdx.y * 128;     // [0, 16384)
    const int gate = n0 >> 10;
    const float* U  = (gate == 0) ? Uf : (gate == 1) ? Ui : (gate == 2) ? Uo : Ug;
    const float* bv = (gate == 0) ? bf : (gate == 1) ? bi : (gate == 2) ? bo : bg;
    const int cg0 = n0 & 1023;

    const int ty = tid >> 4, tx = tid & 15;
    const int mf = ty * 8,  nf = tx * 8;

    float acc[8][8];
    #pragma unroll
    for (int i = 0; i < 8; ++i)
        #pragma unroll
        for (int j = 0; j < 8; ++j) acc[i][j] = 0.f;

    const int lrow = tid >> 1;
    const int lkq  = (tid & 1) * 4;
    const int lkr  = tid >> 5;
    const int lnn  = (tid & 31) * 4;

    for (int k0 = 0; k0 < IND; k0 += 8) {
        float4 xv = *(const float4*)(X + (size_t)(m0 + lrow) * IND + k0 + lkq);
        float4 uv = *(const float4*)(U + (size_t)(k0 + lkr) * HID + cg0 + lnn);
        __syncthreads();
        As[lkq + 0][lrow] = xv.x;
        As[lkq + 1][lrow] = xv.y;
        As[lkq + 2][lrow] = xv.z;
        As[lkq + 3][lrow] = xv.w;
        *(float4*)&Bs[lkr][lnn] = uv;
        __syncthreads();
        #pragma unroll
        for (int kk = 0; kk < 8; ++kk) {
            float4 a0 = *(const float4*)&As[kk][mf];
            float4 a1 = *(const float4*)&As[kk][mf + 4];
            float4 c0 = *(const float4*)&Bs[kk][nf];
            float4 c1 = *(const float4*)&Bs[kk][nf + 4];
            float av[8] = {a0.x, a0.y, a0.z, a0.w, a1.x, a1.y, a1.z, a1.w};
            float bw[8] = {c0.x, c0.y, c0.z, c0.w, c1.x, c1.y, c1.z, c1.w};
            #pragma unroll
            for (int i = 0; i < 8; ++i)
                #pragma unroll
                for (int j = 0; j < 8; ++j)
                    acc[i][j] = fmaf(av[i], bw[j], acc[i][j]);
        }
    }

    #pragma unroll
    for (int i = 0; i < 8; ++i) {
        float* dst = g_xU + (size_t)(m0 + mf + i) * G4 + n0 + nf;
        #pragma unroll
        for (int j = 0; j < 8; ++j)
            dst[j] = acc[i][j] + bv[cg0 + nf + j];
    }
}

// ------------------------------------------------------------------
// Phase B: persistent LSTM recurrence. 128 blocks x 512 threads.
// Block owns 8 hidden units = 32 V columns, col c = 4*u + gate.
// V slice [1024][32] fp32 lives in smem for all 512 steps.
// 8 K-groups of 64 threads; each thread: 4 batches x 4 cols over K=128.
// h_{t-1} read directly from transposed scratch g_hT[t-1][k][b] via
// LDG.128 (one 128B line per (group,k), L1-broadcast within warps).
// Flag-array grid barrier (no atomic RMW contention).
// ------------------------------------------------------------------
#define SMEM_FLOATS (32768 + 8 * 32 * 36 + 256)
#define SMEM_BYTES  (SMEM_FLOATS * 4)

__global__ __launch_bounds__(512) void lstm_kernel(
    float* __restrict__ hseq, float* __restrict__ hlast,
    const float* __restrict__ Vf, const float* __restrict__ Vi,
    const float* __restrict__ Vo, const float* __restrict__ Vg)
{
    extern __shared__ float sm[];
    float* Vs  = sm;                  // [1024*32]  c = 4*u + gate
    float* gts = sm + 32768;          // [8][32][36] padded partials
    float* csm = sm + 32768 + 8 * 32 * 36;  // [32*8] cell state

    const int tid   = threadIdx.x;
    const int bid   = blockIdx.x;
    const int hbase = bid * 8;

    // Load V slice once; column c = 4*u + gate
    for (int idx = tid; idx < HID * 32; idx += 512) {
        int k = idx >> 5, c = idx & 31;
        int u = c >> 2, gate = c & 3;
        const float* Vp = (gate == 0) ? Vf : (gate == 1) ? Vi
                        : (gate == 2) ? Vo : Vg;
        Vs[idx] = Vp[(size_t)k * HID + hbase + u];
    }
    for (int idx = tid; idx < 8 * 32 * 36; idx += 512) gts[idx] = 0.f;
    if (tid < 256) csm[tid] = 0.f;
    __syncthreads();

    const int grp  = tid >> 6;            // K-group 0..7  (K range grp*128..+128)
    const int gtid = tid & 63;
    const int b0   = (gtid & 7) * 4;      // batch fragment
    const int c0   = (gtid >> 3) * 4;     // col fragment (4 gates of one unit)
    const int eu   = tid & 7;             // pointwise: unit  (tid < 256)
    const int eb   = tid >> 3;            // pointwise: batch (tid < 256)

    for (int t = 0; t < SEQ; ++t) {
        // prefetch xU for the pointwise phase (independent of h)
        float xg0 = 0.f, xg1 = 0.f, xg2 = 0.f, xg3 = 0.f;
        if (tid < 256) {
            const float* xrow = g_xU + ((size_t)eb * SEQ + t) * G4 + hbase + eu;
            xg0 = __ldg(xrow);
            xg1 = __ldg(xrow + HID);
            xg2 = __ldg(xrow + 2 * HID);
            xg3 = __ldg(xrow + 3 * HID);
        }

        if (t > 0) {
            float acc[16];
            #pragma unroll
            for (int i = 0; i < 16; ++i) acc[i] = 0.f;

            const float* hp = g_hT + (((size_t)(t - 1) * HID + grp * 128) << 5) + b0;
            const float* vp = Vs + (grp * 128) * 32 + c0;

            #pragma unroll 4
            for (int k = 0; k < 128; ++k) {
                float4 hv = *(const float4*)(hp + k * 32);
                float4 vv = *(const float4*)(vp + k * 32);
                acc[0]  = fmaf(hv.x, vv.x, acc[0]);
                acc[1]  = fmaf(hv.x, vv.y, acc[1]);
                acc[2]  = fmaf(hv.x, vv.z, acc[2]);
                acc[3]  = fmaf(hv.x, vv.w, acc[3]);
                acc[4]  = fmaf(hv.y, vv.x, acc[4]);
                acc[5]  = fmaf(hv.y, vv.y, acc[5]);
                acc[6]  = fmaf(hv.y, vv.z, acc[6]);
                acc[7]  = fmaf(hv.y, vv.w, acc[7]);
                acc[8]  = fmaf(hv.z, vv.x, acc[8]);
                acc[9]  = fmaf(hv.z, vv.y, acc[9]);
                acc[10] = fmaf(hv.z, vv.z, acc[10]);
                acc[11] = fmaf(hv.z, vv.w, acc[11]);
                acc[12] = fmaf(hv.w, vv.x, acc[12]);
                acc[13] = fmaf(hv.w, vv.y, acc[13]);
                acc[14] = fmaf(hv.w, vv.z, acc[14]);
                acc[15] = fmaf(hv.w, vv.w, acc[15]);
            }
            #pragma unroll
            for (int i = 0; i < 4; ++i) {
                *(float4*)&gts[grp * 1152 + (b0 + i) * 36 + c0] =
                    make_float4(acc[i * 4 + 0], acc[i * 4 + 1],
                                acc[i * 4 + 2], acc[i * 4 + 3]);
            }
        }
        __syncthreads();

        // pointwise: thread (eb, eu), tid < 256
        if (tid < 256) {
            float gs0 = xg0, gs1 = xg1, gs2 = xg2, gs3 = xg3;
            #pragma unroll
            for (int g = 0; g < 8; ++g) {
                float4 p = *(const float4*)&gts[g * 1152 + eb * 36 + eu * 4];
                gs0 += p.x; gs1 += p.y; gs2 += p.z; gs3 += p.w;
            }
            float fg = 1.f / (1.f + __expf(-gs0));
            float ig = 1.f / (1.f + __expf(-gs1));
            float og = 1.f / (1.f + __expf(-gs2));
            float gg = tanhf(gs3);
            float c  = fg * csm[eb * 8 + eu] + ig * gg;
            csm[eb * 8 + eu] = c;
            float h = og * tanhf(c);
            const size_t row = (size_t)eb * SEQ + t;
            hseq[row * HID + hbase + eu] = h;
            g_hT[((size_t)t * HID + hbase + eu) * 32 + eb] = h;
            if (t == SEQ - 1) hlast[(size_t)eb * HID + hbase + eu] = h;
        }

        // grid barrier: fence, arrive on own flag, poll all flags in parallel
        __threadfence();
        __syncthreads();
        if (tid == 0) g_flags[bid] = (unsigned)(t + 1);
        if (tid < 128) {
            while (g_flags[tid] <= (unsigned)t) __nanosleep(64);
        }
        __threadfence();
        __syncthreads();
    }
}

// ------------------------------------------------------------------
extern "C" void kernel_launch(void* const* d_in, const int* in_sizes, int n_in,
                              void* d_out, int out_size)
{
    const float* x  = (const float*)d_in[0];
    const float* Uf = (const float*)d_in[1];
    const float* Vf = (const float*)d_in[2];
    const float* bf = (const float*)d_in[3];
    const float* Ui = (const float*)d_in[4];
    const float* Vi = (const float*)d_in[5];
    const float* bi = (const float*)d_in[6];
    const float* Uo = (const float*)d_in[7];
    const float* Vo = (const float*)d_in[8];
    const float* bo = (const float*)d_in[9];
    const float* Ug = (const float*)d_in[10];
    const float* Vg = (const float*)d_in[11];
    const float* bg = (const float*)d_in[12];

    float* out   = (float*)d_out;
    float* hlast = out;                    // [32][1024]
    float* hseq  = out + BSZ * HID;        // [32][512][1024]

    // reset barrier flags deterministically on every invocation
    void* fl = nullptr;
    cudaGetSymbolAddress(&fl, g_flags);
    cudaMemsetAsync(fl, 0, 128 * sizeof(unsigned), 0);

    cudaFuncSetAttribute(lstm_kernel,
                         cudaFuncAttributeMaxDynamicSharedMemorySize, SMEM_BYTES);

    dim3 ggrid(G4 / 128, (BSZ * SEQ) / 128);   // (32, 128)
    gemm_xU_kernel<<<ggrid, 256>>>(x, Uf, Ui, Uo, Ug, bf, bi, bo, bg);

    lstm_kernel<<<128, 512, SMEM_BYTES>>>(hseq, hlast, Vf, Vi, Vo, Vg);
}

// round 3
// speedup vs baseline: 1.6813x; 1.6813x over previous
#include <cuda_runtime.h>
#include <cstddef>

#define BSZ 32
#define SEQ 512
#define IND 512
#define HID 1024
#define G4  4096

// scratch: xU = x @ [Uf|Ui|Uo|Ug] + b   (layout [BSZ*SEQ][4096], 256 MiB)
__device__ float g_xU[(size_t)BSZ * SEQ * G4];
// transposed hidden-state history: g_hT[t][k][b]  (64 MiB)
__device__ float g_hT[(size_t)SEQ * HID * BSZ];
// grid-barrier flags (one word per block, reset each launch)
__device__ volatile unsigned g_flags[128];

__device__ __forceinline__ unsigned smem_u32(const void* p) {
    unsigned a;
    asm("{ .reg .u64 t; cvta.to.shared.u64 t, %1; cvt.u32.u64 %0, t; }"
        : "=r"(a) : "l"(p));
    return a;
}
__device__ __forceinline__ void cp_async16(unsigned dst, const void* src) {
    asm volatile("cp.async.cg.shared.global [%0], [%1], 16;\n"
                 :: "r"(dst), "l"(src));
}
__device__ __forceinline__ void cp_commit() {
    asm volatile("cp.async.commit_group;\n" ::: "memory");
}
template <int N>
__device__ __forceinline__ void cp_wait() {
    asm volatile("cp.async.wait_group %0;\n" :: "n"(N) : "memory");
}
__device__ __forceinline__ float sigmoid_f(float x) {
    return 1.f / (1.f + __expf(-x));
}
__device__ __forceinline__ float tanh_f(float x) {
    return 1.f - 2.f / (__expf(2.f * x) + 1.f);
}

// ------------------------------------------------------------------
// Phase A: xU[m][n] = sum_k X[m][k] * Ucat[k][n] + bcat[n]
// 128x128 block tile, BK=8, 256 threads, 8x8 register tile
// ------------------------------------------------------------------
__global__ __launch_bounds__(256) void gemm_xU_kernel(
    const float* __restrict__ X,
    const float* __restrict__ Uf, const float* __restrict__ Ui,
    const float* __restrict__ Uo, const float* __restrict__ Ug,
    const float* __restrict__ bf, const float* __restrict__ bi,
    const float* __restrict__ bo, const float* __restrict__ bg)
{
    __shared__ float As[8][128];
    __shared__ float Bs[8][128];

    const int tid = threadIdx.x;
    const int n0  = blockIdx.x * 128;
    const int m0  = blockIdx.y * 128;
    const int gate = n0 >> 10;
    const float* U  = (gate == 0) ? Uf : (gate == 1) ? Ui : (gate == 2) ? Uo : Ug;
    const float* bv = (gate == 0) ? bf : (gate == 1) ? bi : (gate == 2) ? bo : bg;
    const int cg0 = n0 & 1023;

    const int ty = tid >> 4, tx = tid & 15;
    const int mf = ty * 8,  nf = tx * 8;

    float acc[8][8];
    #pragma unroll
    for (int i = 0; i < 8; ++i)
        #pragma unroll
        for (int j = 0; j < 8; ++j) acc[i][j] = 0.f;

    const int lrow = tid >> 1;
    const int lkq  = (tid & 1) * 4;
    const int lkr  = tid >> 5;
    const int lnn  = (tid & 31) * 4;

    for (int k0 = 0; k0 < IND; k0 += 8) {
        float4 xv = *(const float4*)(X + (size_t)(m0 + lrow) * IND + k0 + lkq);
        float4 uv = *(const float4*)(U + (size_t)(k0 + lkr) * HID + cg0 + lnn);
        __syncthreads();
        As[lkq + 0][lrow] = xv.x;
        As[lkq + 1][lrow] = xv.y;
        As[lkq + 2][lrow] = xv.z;
        As[lkq + 3][lrow] = xv.w;
        *(float4*)&Bs[lkr][lnn] = uv;
        __syncthreads();
        #pragma unroll
        for (int kk = 0; kk < 8; ++kk) {
            float4 a0 = *(const float4*)&As[kk][mf];
            float4 a1 = *(const float4*)&As[kk][mf + 4];
            float4 c0 = *(const float4*)&Bs[kk][nf];
            float4 c1 = *(const float4*)&Bs[kk][nf + 4];
            float av[8] = {a0.x, a0.y, a0.z, a0.w, a1.x, a1.y, a1.z, a1.w};
            float bw[8] = {c0.x, c0.y, c0.z, c0.w, c1.x, c1.y, c1.z, c1.w};
            #pragma unroll
            for (int i = 0; i < 8; ++i)
                #pragma unroll
                for (int j = 0; j < 8; ++j)
                    acc[i][j] = fmaf(av[i], bw[j], acc[i][j]);
        }
    }

    #pragma unroll
    for (int i = 0; i < 8; ++i) {
        float* dst = g_xU + (size_t)(m0 + mf + i) * G4 + n0 + nf;
        #pragma unroll
        for (int j = 0; j < 8; ++j)
            dst[j] = acc[i][j] + bv[cg0 + nf + j];
    }
}

// ------------------------------------------------------------------
// Phase B: persistent LSTM recurrence. 128 blocks x 512 threads.
// Block owns 8 hidden units = 32 V cols (col c = 4*u + gate).
// V slice [1024][32] resident in smem.
// h_{t-1} streamed from g_hT in 8 chunks of 128 k (16KB, contiguous)
// via cp.async.cg into a double-buffered smem ring.
// 8 K-groups of 64 threads; within a chunk each group covers 16 k.
// Thread frag: 4 batches x 4 cols; acc persists across chunks.
// ------------------------------------------------------------------
#define VS_F    (HID * 32)            // 32768
#define HB_F    (2 * 128 * 32)        // 8192
#define GT_F    (8 * 32 * 36)         // 9216
#define CS_F    256
#define SMEM_FLOATS (VS_F + HB_F + GT_F + CS_F)
#define SMEM_BYTES  (SMEM_FLOATS * 4)

__global__ __launch_bounds__(512) void lstm_kernel(
    float* __restrict__ hseq, float* __restrict__ hlast,
    const float* __restrict__ Vf, const float* __restrict__ Vi,
    const float* __restrict__ Vo, const float* __restrict__ Vg)
{
    extern __shared__ float sm[];
    float* Vs   = sm;                         // [1024][32]
    float* hbuf = sm + VS_F;                  // [2][128][32]
    float* gts  = sm + VS_F + HB_F;           // [8][32][36]
    float* csm  = sm + VS_F + HB_F + GT_F;    // [32][8]

    const int tid   = threadIdx.x;
    const int bid   = blockIdx.x;
    const int hbase = bid * 8;

    // V slice load (once); column c = 4*u + gate
    for (int idx = tid; idx < VS_F; idx += 512) {
        int k = idx >> 5, c = idx & 31;
        int u = c >> 2, gate = c & 3;
        const float* Vp = (gate == 0) ? Vf : (gate == 1) ? Vi
                        : (gate == 2) ? Vo : Vg;
        Vs[idx] = Vp[(size_t)k * HID + hbase + u];
    }
    for (int idx = tid; idx < GT_F; idx += 512) gts[idx] = 0.f;
    if (tid < 256) csm[tid] = 0.f;
    __syncthreads();

    const unsigned hbuf_a = smem_u32(hbuf);
    const int grp  = tid >> 6;            // K-group 0..7
    const int gtid = tid & 63;
    const int b0   = (gtid & 7) * 4;
    const int c0   = (gtid >> 3) * 4;
    const int eu   = tid & 7;             // pointwise unit  (tid < 256)
    const int eb   = tid >> 3;            // pointwise batch (tid < 256)

    for (int t = 0; t < SEQ; ++t) {
        // prefetch xU for the pointwise phase (independent of h)
        float xg0 = 0.f, xg1 = 0.f, xg2 = 0.f, xg3 = 0.f;
        if (tid < 256) {
            const float* xrow = g_xU + ((size_t)eb * SEQ + t) * G4 + hbase + eu;
            xg0 = __ldg(xrow);
            xg1 = __ldg(xrow + HID);
            xg2 = __ldg(xrow + 2 * HID);
            xg3 = __ldg(xrow + 3 * HID);
        }

        if (t > 0) {
            float acc[16];
            #pragma unroll
            for (int i = 0; i < 16; ++i) acc[i] = 0.f;

            const float* hsrc = g_hT + ((size_t)(t - 1) * HID) * 32;

            // prologue: stage chunk 0
            {
                cp_async16(hbuf_a + tid * 16,            hsrc + tid * 4);
                cp_async16(hbuf_a + (tid + 512) * 16,    hsrc + (tid + 512) * 4);
                cp_commit();
            }

            #pragma unroll 1
            for (int j = 0; j < 8; ++j) {
                __syncthreads();   // everyone done computing chunk j-1 (buf reuse)
                if (j < 7) {
                    const float* s = hsrc + (j + 1) * 4096;
                    const unsigned d = hbuf_a + ((j + 1) & 1) * 16384;
                    cp_async16(d + tid * 16,         s + tid * 4);
                    cp_async16(d + (tid + 512) * 16, s + (tid + 512) * 4);
                    cp_commit();
                    cp_wait<1>();
                } else {
                    cp_wait<0>();
                }
                __syncthreads();   // whole chunk j visible

                const float* hp = hbuf + (j & 1) * 4096 + (grp * 16) * 32 + b0;
                const float* vp = Vs + (j * 128 + grp * 16) * 32 + c0;
                #pragma unroll
                for (int kk = 0; kk < 16; ++kk) {
                    float4 hv = *(const float4*)(hp + kk * 32);
                    float4 vv = *(const float4*)(vp + kk * 32);
                    acc[0]  = fmaf(hv.x, vv.x, acc[0]);
                    acc[1]  = fmaf(hv.x, vv.y, acc[1]);
                    acc[2]  = fmaf(hv.x, vv.z, acc[2]);
                    acc[3]  = fmaf(hv.x, vv.w, acc[3]);
                    acc[4]  = fmaf(hv.y, vv.x, acc[4]);
                    acc[5]  = fmaf(hv.y, vv.y, acc[5]);
                    acc[6]  = fmaf(hv.y, vv.z, acc[6]);
                    acc[7]  = fmaf(hv.y, vv.w, acc[7]);
                    acc[8]  = fmaf(hv.z, vv.x, acc[8]);
                    acc[9]  = fmaf(hv.z, vv.y, acc[9]);
                    acc[10] = fmaf(hv.z, vv.z, acc[10]);
                    acc[11] = fmaf(hv.z, vv.w, acc[11]);
                    acc[12] = fmaf(hv.w, vv.x, acc[12]);
                    acc[13] = fmaf(hv.w, vv.y, acc[13]);
                    acc[14] = fmaf(hv.w, vv.z, acc[14]);
                    acc[15] = fmaf(hv.w, vv.w, acc[15]);
                }
            }

            #pragma unroll
            for (int i = 0; i < 4; ++i) {
                *(float4*)&gts[grp * 1152 + (b0 + i) * 36 + c0] =
                    make_float4(acc[i * 4 + 0], acc[i * 4 + 1],
                                acc[i * 4 + 2], acc[i * 4 + 3]);
            }
        }
        __syncthreads();

        // pointwise: thread (eb, eu), tid < 256
        if (tid < 256) {
            float gs0 = xg0, gs1 = xg1, gs2 = xg2, gs3 = xg3;
            #pragma unroll
            for (int g = 0; g < 8; ++g) {
                float4 p = *(const float4*)&gts[g * 1152 + eb * 36 + eu * 4];
                gs0 += p.x; gs1 += p.y; gs2 += p.z; gs3 += p.w;
            }
            float fg = sigmoid_f(gs0);
            float ig = sigmoid_f(gs1);
            float og = sigmoid_f(gs2);
            float gg = tanh_f(gs3);
            float c  = fg * csm[eb * 8 + eu] + ig * gg;
            csm[eb * 8 + eu] = c;
            float h = og * tanh_f(c);
            const size_t row = (size_t)eb * SEQ + t;
            hseq[row * HID + hbase + eu] = h;
            g_hT[((size_t)t * HID + hbase + eu) * 32 + eb] = h;
            if (t == SEQ - 1) hlast[(size_t)eb * HID + hbase + eu] = h;
        }

        // grid barrier: release own flag, poll all flags in parallel
        __threadfence();
        __syncthreads();
        if (tid == 0) g_flags[bid] = (unsigned)(t + 1);
        if (tid < 128) {
            while (g_flags[tid] <= (unsigned)t) __nanosleep(32);
        }
        __threadfence();
        __syncthreads();
    }
}

// ------------------------------------------------------------------
extern "C" void kernel_launch(void* const* d_in, const int* in_sizes, int n_in,
                              void* d_out, int out_size)
{
    const float* x  = (const float*)d_in[0];
    const float* Uf = (const float*)d_in[1];
    const float* Vf = (const float*)d_in[2];
    const float* bf = (const float*)d_in[3];
    const float* Ui = (const float*)d_in[4];
    const float* Vi = (const float*)d_in[5];
    const float* bi = (const float*)d_in[6];
    const float* Uo = (const float*)d_in[7];
    const float* Vo = (const float*)d_in[8];
    const float* bo = (const float*)d_in[9];
    const float* Ug = (const float*)d_in[10];
    const float* Vg = (const float*)d_in[11];
    const float* bg = (const float*)d_in[12];

    float* out   = (float*)d_out;
    float* hlast = out;                    // [32][1024]
    float* hseq  = out + BSZ * HID;        // [32][512][1024]

    void* fl = nullptr;
    cudaGetSymbolAddress(&fl, g_flags);
    cudaMemsetAsync(fl, 0, 128 * sizeof(unsigned), 0);

    cudaFuncSetAttribute(lstm_kernel,
                         cudaFuncAttributeMaxDynamicSharedMemorySize, SMEM_BYTES);

    dim3 ggrid(G4 / 128, (BSZ * SEQ) / 128);   // (32, 128)
    gemm_xU_kernel<<<ggrid, 256>>>(x, Uf, Ui, Uo, Ug, bf, bi, bo, bg);

    lstm_kernel<<<128, 512, SMEM_BYTES>>>(hseq, hlast, Vf, Vi, Vo, Vg);
}

// round 4
// speedup vs baseline: 1.7635x; 1.0489x over previous
#include <cuda_runtime.h>
#include <cstddef>

#define BSZ 32
#define SEQ 512
#define IND 512
#define HID 1024
#define G4  4096

// scratch: xU = x @ [Uf|Ui|Uo|Ug] + b   (layout [BSZ*SEQ][4096], 256 MiB)
__device__ float g_xU[(size_t)BSZ * SEQ * G4];
// transposed hidden-state history: g_hT[t][k][b]  (64 MiB)
__device__ float g_hT[(size_t)SEQ * HID * BSZ];
// grid-barrier flags (one word per block, reset each launch)
__device__ volatile unsigned g_flags[128];

__device__ __forceinline__ unsigned smem_u32(const void* p) {
    unsigned a;
    asm("{ .reg .u64 t; cvta.to.shared.u64 t, %1; cvt.u32.u64 %0, t; }"
        : "=r"(a) : "l"(p));
    return a;
}
__device__ __forceinline__ void cp_async16(unsigned dst, const void* src) {
    asm volatile("cp.async.cg.shared.global [%0], [%1], 16;\n"
                 :: "r"(dst), "l"(src));
}
__device__ __forceinline__ void cp_commit() {
    asm volatile("cp.async.commit_group;\n" ::: "memory");
}
template <int N>
__device__ __forceinline__ void cp_wait() {
    asm volatile("cp.async.wait_group %0;\n" :: "n"(N) : "memory");
}
__device__ __forceinline__ float sigmoid_f(float x) {
    return 1.f / (1.f + __expf(-x));
}
__device__ __forceinline__ float tanh_f(float x) {
    return 1.f - 2.f / (__expf(2.f * x) + 1.f);
}

// ------------------------------------------------------------------
// Phase A: xU[m][n] = sum_k X[m][k] * Ucat[k][n] + bcat[n]
// 128x128 block tile, BK=8, 256 threads, 8x8 register tile
// ------------------------------------------------------------------
__global__ __launch_bounds__(256) void gemm_xU_kernel(
    const float* __restrict__ X,
    const float* __restrict__ Uf, const float* __restrict__ Ui,
    const float* __restrict__ Uo, const float* __restrict__ Ug,
    const float* __restrict__ bf, const float* __restrict__ bi,
    const float* __restrict__ bo, const float* __restrict__ bg)
{
    __shared__ float As[8][128];
    __shared__ float Bs[8][128];

    const int tid = threadIdx.x;
    const int n0  = blockIdx.x * 128;
    const int m0  = blockIdx.y * 128;
    const int gate = n0 >> 10;
    const float* U  = (gate == 0) ? Uf : (gate == 1) ? Ui : (gate == 2) ? Uo : Ug;
    const float* bv = (gate == 0) ? bf : (gate == 1) ? bi : (gate == 2) ? bo : bg;
    const int cg0 = n0 & 1023;

    const int ty = tid >> 4, tx = tid & 15;
    const int mf = ty * 8,  nf = tx * 8;

    float acc[8][8];
    #pragma unroll
    for (int i = 0; i < 8; ++i)
        #pragma unroll
        for (int j = 0; j < 8; ++j) acc[i][j] = 0.f;

    const int lrow = tid >> 1;
    const int lkq  = (tid & 1) * 4;
    const int lkr  = tid >> 5;
    const int lnn  = (tid & 31) * 4;

    for (int k0 = 0; k0 < IND; k0 += 8) {
        float4 xv = *(const float4*)(X + (size_t)(m0 + lrow) * IND + k0 + lkq);
        float4 uv = *(const float4*)(U + (size_t)(k0 + lkr) * HID + cg0 + lnn);
        __syncthreads();
        As[lkq + 0][lrow] = xv.x;
        As[lkq + 1][lrow] = xv.y;
        As[lkq + 2][lrow] = xv.z;
        As[lkq + 3][lrow] = xv.w;
        *(float4*)&Bs[lkr][lnn] = uv;
        __syncthreads();
        #pragma unroll
        for (int kk = 0; kk < 8; ++kk) {
            float4 a0 = *(const float4*)&As[kk][mf];
            float4 a1 = *(const float4*)&As[kk][mf + 4];
            float4 c0 = *(const float4*)&Bs[kk][nf];
            float4 c1 = *(const float4*)&Bs[kk][nf + 4];
            float av[8] = {a0.x, a0.y, a0.z, a0.w, a1.x, a1.y, a1.z, a1.w};
            float bw[8] = {c0.x, c0.y, c0.z, c0.w, c1.x, c1.y, c1.z, c1.w};
            #pragma unroll
            for (int i = 0; i < 8; ++i)
                #pragma unroll
                for (int j = 0; j < 8; ++j)
                    acc[i][j] = fmaf(av[i], bw[j], acc[i][j]);
        }
    }

    #pragma unroll
    for (int i = 0; i < 8; ++i) {
        float* dst = g_xU + (size_t)(m0 + mf + i) * G4 + n0 + nf;
        #pragma unroll
        for (int j = 0; j < 8; ++j)
            dst[j] = acc[i][j] + bv[cg0 + nf + j];
    }
}

// ------------------------------------------------------------------
// Phase B: persistent LSTM recurrence. 128 blocks x 512 threads.
// Block owns 8 hidden units = 32 V cols (col c = 4*u + gate).
// V slice [1024][32] resident in smem.
// h_{t-1} streamed from g_hT in 8 chunks of 128 k (16KB, contiguous)
// via cp.async.cg into a double-buffered smem ring.
// 8 K-groups of 64 threads; within a chunk each group covers 16 k.
// Thread frag: 4 batches x 4 cols; acc persists across chunks.
// ------------------------------------------------------------------
#define VS_F    (HID * 32)            // 32768
#define HB_F    (2 * 128 * 32)        // 8192
#define GT_F    (8 * 32 * 36)         // 9216
#define CS_F    256
#define SMEM_FLOATS (VS_F + HB_F + GT_F + CS_F)
#define SMEM_BYTES  (SMEM_FLOATS * 4)

__global__ __launch_bounds__(512) void lstm_kernel(
    float* __restrict__ hseq, float* __restrict__ hlast,
    const float* __restrict__ Vf, const float* __restrict__ Vi,
    const float* __restrict__ Vo, const float* __restrict__ Vg)
{
    extern __shared__ float sm[];
    float* Vs   = sm;                         // [1024][32]
    float* hbuf = sm + VS_F;                  // [2][128][32]
    float* gts  = sm + VS_F + HB_F;           // [8][32][36]
    float* csm  = sm + VS_F + HB_F + GT_F;    // [32][8]

    const int tid   = threadIdx.x;
    const int bid   = blockIdx.x;
    const int hbase = bid * 8;

    // V slice load (once); column c = 4*u + gate
    for (int idx = tid; idx < VS_F; idx += 512) {
        int k = idx >> 5, c = idx & 31;
        int u = c >> 2, gate = c & 3;
        const float* Vp = (gate == 0) ? Vf : (gate == 1) ? Vi
                        : (gate == 2) ? Vo : Vg;
        Vs[idx] = Vp[(size_t)k * HID + hbase + u];
    }
    for (int idx = tid; idx < GT_F; idx += 512) gts[idx] = 0.f;
    if (tid < 256) csm[tid] = 0.f;
    __syncthreads();

    const unsigned hbuf_a = smem_u32(hbuf);
    const int grp  = tid >> 6;            // K-group 0..7
    const int gtid = tid & 63;
    const int b0   = (gtid & 7) * 4;
    const int c0   = (gtid >> 3) * 4;
    const int eu   = tid & 7;             // pointwise unit  (tid < 256)
    const int eb   = tid >> 3;            // pointwise batch (tid < 256)

    for (int t = 0; t < SEQ; ++t) {
        // prefetch xU for the pointwise phase (independent of h)
        float xg0 = 0.f, xg1 = 0.f, xg2 = 0.f, xg3 = 0.f;
        if (tid < 256) {
            const float* xrow = g_xU + ((size_t)eb * SEQ + t) * G4 + hbase + eu;
            xg0 = __ldg(xrow);
            xg1 = __ldg(xrow + HID);
            xg2 = __ldg(xrow + 2 * HID);
            xg3 = __ldg(xrow + 3 * HID);
        }

        if (t > 0) {
            float acc[16];
            #pragma unroll
            for (int i = 0; i < 16; ++i) acc[i] = 0.f;

            const float* hsrc = g_hT + ((size_t)(t - 1) * HID) * 32;

            // prologue: stage chunk 0
            {
                cp_async16(hbuf_a + tid * 16,            hsrc + tid * 4);
                cp_async16(hbuf_a + (tid + 512) * 16,    hsrc + (tid + 512) * 4);
                cp_commit();
            }

            #pragma unroll 1
            for (int j = 0; j < 8; ++j) {
                __syncthreads();   // everyone done computing chunk j-1 (buf reuse)
                if (j < 7) {
                    const float* s = hsrc + (j + 1) * 4096;
                    const unsigned d = hbuf_a + ((j + 1) & 1) * 16384;
                    cp_async16(d + tid * 16,         s + tid * 4);
                    cp_async16(d + (tid + 512) * 16, s + (tid + 512) * 4);
                    cp_commit();
                    cp_wait<1>();
                } else {
                    cp_wait<0>();
                }
                __syncthreads();   // whole chunk j visible

                const float* hp = hbuf + (j & 1) * 4096 + (grp * 16) * 32 + b0;
                const float* vp = Vs + (j * 128 + grp * 16) * 32 + c0;
                #pragma unroll
                for (int kk = 0; kk < 16; ++kk) {
                    float4 hv = *(const float4*)(hp + kk * 32);
                    float4 vv = *(const float4*)(vp + kk * 32);
                    acc[0]  = fmaf(hv.x, vv.x, acc[0]);
                    acc[1]  = fmaf(hv.x, vv.y, acc[1]);
                    acc[2]  = fmaf(hv.x, vv.z, acc[2]);
                    acc[3]  = fmaf(hv.x, vv.w, acc[3]);
                    acc[4]  = fmaf(hv.y, vv.x, acc[4]);
                    acc[5]  = fmaf(hv.y, vv.y, acc[5]);
                    acc[6]  = fmaf(hv.y, vv.z, acc[6]);
                    acc[7]  = fmaf(hv.y, vv.w, acc[7]);
                    acc[8]  = fmaf(hv.z, vv.x, acc[8]);
                    acc[9]  = fmaf(hv.z, vv.y, acc[9]);
                    acc[10] = fmaf(hv.z, vv.z, acc[10]);
                    acc[11] = fmaf(hv.z, vv.w, acc[11]);
                    acc[12] = fmaf(hv.w, vv.x, acc[12]);
                    acc[13] = fmaf(hv.w, vv.y, acc[13]);
                    acc[14] = fmaf(hv.w, vv.z, acc[14]);
                    acc[15] = fmaf(hv.w, vv.w, acc[15]);
                }
            }

            #pragma unroll
            for (int i = 0; i < 4; ++i) {
                *(float4*)&gts[grp * 1152 + (b0 + i) * 36 + c0] =
                    make_float4(acc[i * 4 + 0], acc[i * 4 + 1],
                                acc[i * 4 + 2], acc[i * 4 + 3]);
            }
        }
        __syncthreads();

        // pointwise: thread (eb, eu), tid < 256
        if (tid < 256) {
            float gs0 = xg0, gs1 = xg1, gs2 = xg2, gs3 = xg3;
            #pragma unroll
            for (int g = 0; g < 8; ++g) {
                float4 p = *(const float4*)&gts[g * 1152 + eb * 36 + eu * 4];
                gs0 += p.x; gs1 += p.y; gs2 += p.z; gs3 += p.w;
            }
            float fg = sigmoid_f(gs0);
            float ig = sigmoid_f(gs1);
            float og = sigmoid_f(gs2);
            float gg = tanh_f(gs3);
            float c  = fg * csm[eb * 8 + eu] + ig * gg;
            csm[eb * 8 + eu] = c;
            float h = og * tanh_f(c);
            const size_t row = (size_t)eb * SEQ + t;
            hseq[row * HID + hbase + eu] = h;
            g_hT[((size_t)t * HID + hbase + eu) * 32 + eb] = h;
            if (t == SEQ - 1) hlast[(size_t)eb * HID + hbase + eu] = h;
        }

        // grid barrier: release own flag, poll all flags in parallel
        __threadfence();
        __syncthreads();
        if (tid == 0) g_flags[bid] = (unsigned)(t + 1);
        if (tid < 128) {
            while (g_flags[tid] <= (unsigned)t) __nanosleep(32);
        }
        __threadfence();
        __syncthreads();
    }
}

// ------------------------------------------------------------------
extern "C" void kernel_launch(void* const* d_in, const int* in_sizes, int n_in,
                              void* d_out, int out_size)
{
    const float* x  = (const float*)d_in[0];
    const float* Uf = (const float*)d_in[1];
    const float* Vf = (const float*)d_in[2];
    const float* bf = (const float*)d_in[3];
    const float* Ui = (const float*)d_in[4];
    const float* Vi = (const float*)d_in[5];
    const float* bi = (const float*)d_in[6];
    const float* Uo = (const float*)d_in[7];
    const float* Vo = (const float*)d_in[8];
    const float* bo = (const float*)d_in[9];
    const float* Ug = (const float*)d_in[10];
    const float* Vg = (const float*)d_in[11];
    const float* bg = (const float*)d_in[12];

    float* out   = (float*)d_out;
    float* hlast = out;                    // [32][1024]
    float* hseq  = out + BSZ * HID;        // [32][512][1024]

    void* fl = nullptr;
    cudaGetSymbolAddress(&fl, g_flags);
    cudaMemsetAsync(fl, 0, 128 * sizeof(unsigned), 0);

    cudaFuncSetAttribute(lstm_kernel,
                         cudaFuncAttributeMaxDynamicSharedMemorySize, SMEM_BYTES);

    dim3 ggrid(G4 / 128, (BSZ * SEQ) / 128);   // (32, 128)
    gemm_xU_kernel<<<ggrid, 256>>>(x, Uf, Ui, Uo, Ug, bf, bi, bo, bg);

    lstm_kernel<<<128, 512, SMEM_BYTES>>>(hseq, hlast, Vf, Vi, Vo, Vg);
}

// round 7
// speedup vs baseline: 2.7095x; 1.5364x over previous
#include <cuda_runtime.h>
#include <cstdint>
#include <cstddef>

#define BSZ 32
#define SEQ 512
#define IND 512
#define HID 1024
#define G4  4096
#define NBLK 128

// ---------------- device globals ----------------
__device__ float g_xU[(size_t)BSZ * SEQ * G4];     // [b*512+t][4096]
__device__ float g_Xc[(size_t)BSZ * SEQ * IND];    // tf32-rounded x
__device__ float g_Uc[(size_t)IND * G4];           // tf32 U concat [k][4096]
__device__ float g_bc[G4];                          // bias concat
__device__ float g_Vf[(size_t)NBLK * 32768];       // V fragments per block
__device__ float g_hA[2][NBLK * 256];              // h in A-fragment order
__device__ volatile unsigned g_flags[NBLK];

// ---------------- helpers ----------------
__device__ __forceinline__ uint32_t smem_u32(const void* p) {
    uint32_t a;
    asm("{ .reg .u64 t; cvta.to.shared.u64 t, %1; cvt.u32.u64 %0, t; }" : "=r"(a) : "l"(p));
    return a;
}
__device__ __forceinline__ void cp_async16(uint32_t dst, const void* src) {
    asm volatile("cp.async.cg.shared.global [%0], [%1], 16;" :: "r"(dst), "l"(src));
}
__device__ __forceinline__ void cp_commit() { asm volatile("cp.async.commit_group;" ::: "memory"); }
template <int N> __device__ __forceinline__ void cp_wait() {
    asm volatile("cp.async.wait_group %0;" :: "n"(N) : "memory");
}
__device__ __forceinline__ float to_tf32(float x) {
    uint32_t r;
    asm("cvt.rna.tf32.f32 %0, %1;" : "=r"(r) : "f"(x));
    return __uint_as_float(r);
}
__device__ __forceinline__ void mma8(float& d0, float& d1, float& d2, float& d3,
                                     uint32_t a0, uint32_t a1, uint32_t a2, uint32_t a3,
                                     uint32_t b0, uint32_t b1) {
    asm volatile("mma.sync.aligned.m16n8k8.row.col.f32.tf32.tf32.f32 "
                 "{%0,%1,%2,%3}, {%4,%5,%6,%7}, {%8,%9}, {%0,%1,%2,%3};"
                 : "+f"(d0), "+f"(d1), "+f"(d2), "+f"(d3)
                 : "r"(a0), "r"(a1), "r"(a2), "r"(a3), "r"(b0), "r"(b1));
}
__device__ __forceinline__ float sigmoid_f(float x) { return 1.f / (1.f + __expf(-x)); }
__device__ __forceinline__ float tanh_f(float x) { return 1.f - 2.f / (__expf(2.f * x) + 1.f); }

// ---------------- conversion kernels ----------------
__global__ void conv_x(const float* __restrict__ x) {
    size_t i = (size_t)blockIdx.x * blockDim.x + threadIdx.x;
    size_t n = (size_t)BSZ * SEQ * IND;
    for (; i < n; i += (size_t)gridDim.x * blockDim.x) g_Xc[i] = to_tf32(x[i]);
}
__global__ void conv_u(const float* __restrict__ Uf, const float* __restrict__ Ui,
                       const float* __restrict__ Uo, const float* __restrict__ Ug,
                       const float* __restrict__ bf, const float* __restrict__ bi,
                       const float* __restrict__ bo, const float* __restrict__ bg) {
    size_t i = (size_t)blockIdx.x * blockDim.x + threadIdx.x;
    size_t n = (size_t)IND * G4;
    for (; i < n; i += (size_t)gridDim.x * blockDim.x) {
        int k = (int)(i >> 12), col = (int)(i & 4095);
        int g = col >> 10, u = col & 1023;
        const float* U = (g == 0) ? Uf : (g == 1) ? Ui : (g == 2) ? Uo : Ug;
        g_Uc[i] = to_tf32(U[(size_t)k * HID + u]);
        if (i < G4) {
            const float* bv = (g == 0) ? bf : (g == 1) ? bi : (g == 2) ? bo : bg;
            g_bc[i] = bv[u];
        }
    }
}
// V fragments: g_Vf[bid][ks][nt][lane][2]; c = nt*8 + lane/4 = 4*u + gate
__global__ __launch_bounds__(256) void make_vfrag(
    const float* __restrict__ Vf, const float* __restrict__ Vi,
    const float* __restrict__ Vo, const float* __restrict__ Vg) {
    const int bid = blockIdx.x;
    float* dst = g_Vf + (size_t)bid * 32768;
    for (int e = threadIdx.x; e < 32768; e += 256) {
        int wd = e & 1, lane = (e >> 1) & 31, nt = (e >> 6) & 3, ks = e >> 8;
        int k = ks * 8 + (lane & 3) + wd * 4;
        int c = nt * 8 + (lane >> 2);
        int u = c >> 2, g = c & 3;
        const float* V = (g == 0) ? Vf : (g == 1) ? Vi : (g == 2) ? Vo : Vg;
        dst[e] = to_tf32(V[(size_t)k * HID + bid * 8 + u]);
    }
}

// ---------------- Phase A: mma.sync tf32 GEMM ----------------
// 128m x 128n block tile, BK=32, 256 thr (8 warps: 2m x 4n), warp 64x32.
#define PA_SA0 0
#define PA_SA1 18432
#define PA_SB0 36864
#define PA_SB1 53760
#define PA_SMEM 70656

__global__ __launch_bounds__(256) void gemm_xU_mma() {
    extern __shared__ char smx[];
    const uint32_t sb = smem_u32(smx);
    const int tid = threadIdx.x;
    const int n0 = blockIdx.x * 128, m0 = blockIdx.y * 128;
    const int w = tid >> 5, l = tid & 31;
    const int wm = w >> 2, wn = w & 3;

    float acc[4][4][4];
    #pragma unroll
    for (int i = 0; i < 4; ++i)
        #pragma unroll
        for (int j = 0; j < 4; ++j)
            #pragma unroll
            for (int r = 0; r < 4; ++r) acc[i][j][r] = 0.f;

    auto stage = [&](int c) {
        const uint32_t sa = sb + ((c & 1) ? PA_SA1 : PA_SA0);
        const uint32_t sbm = sb + ((c & 1) ? PA_SB1 : PA_SB0);
        #pragma unroll
        for (int i = 0; i < 4; ++i) {
            int e = tid + i * 256;
            int r = e >> 3, kq = e & 7;
            cp_async16(sa + (uint32_t)(r * 144 + kq * 16),
                       g_Xc + (size_t)(m0 + r) * IND + c * 32 + kq * 4);
        }
        #pragma unroll
        for (int i = 0; i < 4; ++i) {
            int e = tid + i * 256;
            int r = e >> 5, nq = e & 31;
            cp_async16(sbm + (uint32_t)(r * 528 + nq * 16),
                       g_Uc + (size_t)(c * 32 + r) * G4 + n0 + nq * 4);
        }
    };

    stage(0); cp_commit();
    #pragma unroll 1
    for (int c = 0; c < 16; ++c) {
        __syncthreads();
        if (c < 15) { stage(c + 1); cp_commit(); cp_wait<1>(); }
        else cp_wait<0>();
        __syncthreads();
        const uint32_t* As = (const uint32_t*)(smx + ((c & 1) ? PA_SA1 : PA_SA0));
        const uint32_t* Bs = (const uint32_t*)(smx + ((c & 1) ? PA_SB1 : PA_SB0));
        #pragma unroll
        for (int kk = 0; kk < 32; kk += 8) {
            uint32_t a[4][4];
            #pragma unroll
            for (int mt = 0; mt < 4; ++mt) {
                int r = wm * 64 + mt * 16 + (l >> 2);
                a[mt][0] = As[r * 36 + kk + (l & 3)];
                a[mt][1] = As[(r + 8) * 36 + kk + (l & 3)];
                a[mt][2] = As[r * 36 + kk + 4 + (l & 3)];
                a[mt][3] = As[(r + 8) * 36 + kk + 4 + (l & 3)];
            }
            #pragma unroll
            for (int nt = 0; nt < 4; ++nt) {
                int n = wn * 32 + nt * 8 + (l >> 2);
                uint32_t b0 = Bs[(kk + (l & 3)) * 132 + n];
                uint32_t b1 = Bs[(kk + 4 + (l & 3)) * 132 + n];
                #pragma unroll
                for (int mt = 0; mt < 4; ++mt)
                    mma8(acc[mt][nt][0], acc[mt][nt][1], acc[mt][nt][2], acc[mt][nt][3],
                         a[mt][0], a[mt][1], a[mt][2], a[mt][3], b0, b1);
            }
        }
    }
    // epilogue: + bias, store
    #pragma unroll
    for (int mt = 0; mt < 4; ++mt) {
        #pragma unroll
        for (int nt = 0; nt < 4; ++nt) {
            int m = m0 + wm * 64 + mt * 16 + (l >> 2);
            int n = n0 + wn * 32 + nt * 8 + (l & 3) * 2;
            float2 bv = *(const float2*)&g_bc[n];
            float2 v0 = make_float2(acc[mt][nt][0] + bv.x, acc[mt][nt][1] + bv.y);
            float2 v1 = make_float2(acc[mt][nt][2] + bv.x, acc[mt][nt][3] + bv.y);
            *(float2*)&g_xU[(size_t)m * G4 + n] = v0;
            *(float2*)&g_xU[(size_t)(m + 8) * G4 + n] = v1;
        }
    }
}

// ---------------- Phase B: persistent mma.sync recurrence ----------------
// smem: Vf 128KB | hbuf 2x16KB | gpart 18KB
#define SM_VF 0
#define SM_HB 131072
#define SM_GP 163840
#define SMEM_BYTES (163840 + 18432)

__global__ __launch_bounds__(512) void lstm_mma(float* __restrict__ hseq,
                                                float* __restrict__ hlast)
{
    extern __shared__ char smx[];
    const uint32_t sb = smem_u32(smx);
    float* Vfs = (float*)smx;
    float* gpart = (float*)(smx + SM_GP);
    const int tid = threadIdx.x, bid = blockIdx.x;
    const int hbase = bid * 8;

    // load V fragments (once)
    {
        const float4* src = (const float4*)(g_Vf + (size_t)bid * 32768);
        float4* dst = (float4*)Vfs;
        for (int i = tid; i < 8192; i += 512) dst[i] = src[i];
    }
    for (int i = tid; i < 4608; i += 512) gpart[i] = 0.f;
    __syncthreads();

    const int w = tid >> 5, l = tid & 31;
    const int nt = w & 3, ksub = w >> 2;
    const int pb = tid >> 3, pu = tid & 7;   // pointwise mapping (tid < 256)
    float cr = 0.f;

    for (int t = 0; t < SEQ; ++t) {
        float xg0 = 0.f, xg1 = 0.f, xg2 = 0.f, xg3 = 0.f;
        if (tid < 256) {
            const float* xrow = g_xU + ((size_t)pb * SEQ + t) * G4 + hbase + pu;
            xg0 = __ldg(xrow);
            xg1 = __ldg(xrow + HID);
            xg2 = __ldg(xrow + 2 * HID);
            xg3 = __ldg(xrow + 3 * HID);
        }

        if (t > 0) {
            float aA[4] = {0.f, 0.f, 0.f, 0.f};   // batches 0..15
            float aB[4] = {0.f, 0.f, 0.f, 0.f};   // batches 16..31
            const float4* hsrc = (const float4*)(g_hA[(t + 1) & 1]);

            auto stageH = [&](int j) {
                const uint32_t d = sb + SM_HB + (uint32_t)(j & 1) * 16384u;
                cp_async16(d + (uint32_t)tid * 16u, hsrc + j * 1024 + tid);
                cp_async16(d + (uint32_t)(tid + 512) * 16u, hsrc + j * 1024 + tid + 512);
            };
            stageH(0); cp_commit();

            #pragma unroll 1
            for (int j = 0; j < 8; ++j) {
                __syncthreads();
                if (j < 7) { stageH(j + 1); cp_commit(); cp_wait<1>(); }
                else cp_wait<0>();
                __syncthreads();
                const float4* hb = (const float4*)(smx + SM_HB + (j & 1) * 16384);
                #pragma unroll
                for (int q = 0; q < 4; ++q) {
                    int ksl = ksub * 4 + q;
                    float4 A0 = hb[ksl * 64 + l];
                    float4 A1 = hb[ksl * 64 + 32 + l];
                    int ks = j * 16 + ksl;
                    float2 Bv = *(const float2*)(Vfs + ((size_t)(ks * 4 + nt) * 32 + l) * 2);
                    uint32_t b0 = __float_as_uint(Bv.x), b1 = __float_as_uint(Bv.y);
                    mma8(aA[0], aA[1], aA[2], aA[3],
                         __float_as_uint(A0.x), __float_as_uint(A0.y),
                         __float_as_uint(A0.z), __float_as_uint(A0.w), b0, b1);
                    mma8(aB[0], aB[1], aB[2], aB[3],
                         __float_as_uint(A1.x), __float_as_uint(A1.y),
                         __float_as_uint(A1.z), __float_as_uint(A1.w), b0, b1);
                }
            }
            // partials -> smem
            int cb = nt * 8 + (l & 3) * 2, r0 = l >> 2;
            float* gp = gpart + ksub * 1152;
            *(float2*)&gp[r0 * 36 + cb]        = make_float2(aA[0], aA[1]);
            *(float2*)&gp[(r0 + 8) * 36 + cb]  = make_float2(aA[2], aA[3]);
            *(float2*)&gp[(r0 + 16) * 36 + cb] = make_float2(aB[0], aB[1]);
            *(float2*)&gp[(r0 + 24) * 36 + cb] = make_float2(aB[2], aB[3]);
        }
        __syncthreads();

        if (tid < 256) {
            float g0 = xg0, g1 = xg1, g2 = xg2, g3 = xg3;
            #pragma unroll
            for (int ks = 0; ks < 4; ++ks) {
                float4 p = *(const float4*)&gpart[ks * 1152 + pb * 36 + pu * 4];
                g0 += p.x; g1 += p.y; g2 += p.z; g3 += p.w;
            }
            float fg = sigmoid_f(g0), ig = sigmoid_f(g1);
            float og = sigmoid_f(g2), gg = tanh_f(g3);
            cr = fg * cr + ig * gg;
            float h = og * tanh_f(cr);
            hseq[((size_t)pb * SEQ + t) * HID + hbase + pu] = h;
            if (t == SEQ - 1) hlast[(size_t)pb * HID + hbase + pu] = h;
            // store h in A-fragment order (tf32-rounded)
            int mt = pb >> 4, br = pb & 15;
            int lane = (br & 7) * 4 + (pu & 3);
            int wd = (pu < 4) ? ((br & 8) ? 1 : 0) : ((br & 8) ? 3 : 2);
            g_hA[t & 1][((bid * 2 + mt) * 32 + lane) * 4 + wd] = to_tf32(h);
        }

        // grid barrier
        __threadfence();
        __syncthreads();
        if (tid == 0) g_flags[bid] = (unsigned)(t + 1);
        if (tid < NBLK) {
            while (g_flags[tid] <= (unsigned)t) __nanosleep(32);
        }
        __threadfence();
        __syncthreads();
    }
}

// ---------------- launch ----------------
extern "C" void kernel_launch(void* const* d_in, const int* in_sizes, int n_in,
                              void* d_out, int out_size)
{
    const float* x  = (const float*)d_in[0];
    const float* Uf = (const float*)d_in[1];
    const float* Vf = (const float*)d_in[2];
    const float* bf = (const float*)d_in[3];
    const float* Ui = (const float*)d_in[4];
    const float* Vi = (const float*)d_in[5];
    const float* bi = (const float*)d_in[6];
    const float* Uo = (const float*)d_in[7];
    const float* Vo = (const float*)d_in[8];
    const float* bo = (const float*)d_in[9];
    const float* Ug = (const float*)d_in[10];
    const float* Vg = (const float*)d_in[11];
    const float* bg = (const float*)d_in[12];

    float* out   = (float*)d_out;
    float* hlast = out;                 // [32][1024]
    float* hseq  = out + BSZ * HID;     // [32][512][1024]

    void* fl = nullptr;
    cudaGetSymbolAddress(&fl, g_flags);
    cudaMemsetAsync(fl, 0, NBLK * sizeof(unsigned), 0);

    cudaFuncSetAttribute(gemm_xU_mma, cudaFuncAttributeMaxDynamicSharedMemorySize, PA_SMEM);
    cudaFuncSetAttribute(lstm_mma, cudaFuncAttributeMaxDynamicSharedMemorySize, SMEM_BYTES);

    conv_x<<<512, 256>>>(x);
    conv_u<<<512, 256>>>(Uf, Ui, Uo, Ug, bf, bi, bo, bg);
    make_vfrag<<<NBLK, 256>>>(Vf, Vi, Vo, Vg);

    dim3 ggrid(G4 / 128, (BSZ * SEQ) / 128);   // (32, 128)
    gemm_xU_mma<<<ggrid, 256, PA_SMEM>>>();
    lstm_mma<<<NBLK, 512, SMEM_BYTES>>>(hseq, hlast);
}